// round 7
// baseline (speedup 1.0000x reference)
#include <cuda_runtime.h>
#include <cuda_fp16.h>
#include <cstdint>

typedef uint32_t u32;

static constexpr int NB = 32, NN = 128, DD = 64;

// At in mma-A-fragment layout: [b][jblock(8)][ks(8)][lane(32)] = uint4
// fragment regs per thread: a0=(r, k:c2,c2+1), a1=(r+8, k), a2=(r, k+8), a3=(r+8, k+8)
// where r=lane>>2, c2=2*(lane&3), j = jblock*16 + r, k = ks*16 + c2, At[j][k]=A[b][k][j].
__device__ __align__(16) uint4 g_Afrag[32 * 8 * 8 * 32];   // 1 MB

// ---------------- helpers ----------------
__device__ __forceinline__ u32 smem_u32(const void* p) {
    u32 a;
    asm("{ .reg .u64 t; cvta.to.shared.u64 t, %1; cvt.u32.u64 %0, t; }" : "=r"(a) : "l"(p));
    return a;
}
__device__ __forceinline__ u32 pack_h16(float lo, float hi) {
    u32 r;
    asm("cvt.rn.f16x2.f32 %0, %1, %2;" : "=r"(r) : "f"(hi), "f"(lo));
    return r;
}
__device__ __forceinline__ void sts32(u32 a, u32 v) {
    asm volatile("st.shared.b32 [%0], %1;" :: "r"(a), "r"(v) : "memory");
}
__device__ __forceinline__ void sts64(u32 a, u32 x, u32 y) {
    asm volatile("st.shared.v2.b32 [%0], {%1,%2};" :: "r"(a), "r"(x), "r"(y) : "memory");
}
__device__ __forceinline__ void lds64f(float& x, float& y, u32 a) {
    asm volatile("ld.shared.v2.f32 {%0,%1}, [%2];" : "=f"(x), "=f"(y) : "r"(a));
}
__device__ __forceinline__ void ldsm4(u32* f, u32 a) {
    asm volatile("ldmatrix.sync.aligned.m8n8.x4.shared.b16 {%0,%1,%2,%3}, [%4];"
                 : "=r"(f[0]), "=r"(f[1]), "=r"(f[2]), "=r"(f[3]) : "r"(a));
}
__device__ __forceinline__ void ldsm4t(u32* f, u32 a) {
    asm volatile("ldmatrix.sync.aligned.m8n8.x4.trans.shared.b16 {%0,%1,%2,%3}, [%4];"
                 : "=r"(f[0]), "=r"(f[1]), "=r"(f[2]), "=r"(f[3]) : "r"(a));
}
__device__ __forceinline__ void mma_f16(float* c, const u32* a, const u32* b) {
    asm volatile(
        "mma.sync.aligned.m16n8k16.row.col.f32.f16.f16.f32 "
        "{%0,%1,%2,%3}, {%4,%5,%6,%7}, {%8,%9}, {%0,%1,%2,%3};"
        : "+f"(c[0]), "+f"(c[1]), "+f"(c[2]), "+f"(c[3])
        : "r"(a[0]), "r"(a[1]), "r"(a[2]), "r"(a[3]), "r"(b[0]), "r"(b[1]));
}

// ---------------- smem layout ----------------
static constexpr u32 RS64  = 144;   // 64-wide fp16 tile row stride (bytes)

static constexpr u32 OFF_X  = 0;        // 18432
static constexpr u32 OFF_W1 = 18432;    // 9216
static constexpr u32 OFF_W2 = 27648;    // 9216
static constexpr u32 OFF_H2 = 36864;    // 18432
static constexpr u32 OFF_B1 = 55296;    // 256
static constexpr u32 OFF_B2 = 55552;    // 256
static constexpr u32 SMEM_BYTES = 55808;

static constexpr int I_PER_CTA = 4;

// =============== prep: A[b][k][j] -> fragment-layout fp16 image ===============
__global__ void prep_Afrag(const float* __restrict__ A)
{
    int id = blockIdx.x * blockDim.x + threadIdx.x;   // 65536 total
    int lane = id & 31;
    int ks   = (id >> 5) & 7;
    int jb   = (id >> 8) & 7;
    int b    = id >> 11;
    int r  = lane >> 2;
    int c2 = (lane & 3) * 2;
    int j = jb * 16 + r;
    int k = ks * 16 + c2;
    const float* Ab = A + (size_t)b * NN * NN;
    uint4 v;
    v.x = pack_h16(Ab[(size_t)k * NN + j],           Ab[(size_t)(k + 1) * NN + j]);
    v.y = pack_h16(Ab[(size_t)k * NN + j + 8],       Ab[(size_t)(k + 1) * NN + j + 8]);
    v.z = pack_h16(Ab[(size_t)(k + 8) * NN + j],     Ab[(size_t)(k + 9) * NN + j]);
    v.w = pack_h16(Ab[(size_t)(k + 8) * NN + j + 8], Ab[(size_t)(k + 9) * NN + j + 8]);
    g_Afrag[id] = v;
}

// =============== main fused kernel ===============
__global__ __launch_bounds__(256, 3)
void crosssubg_mma_kernel(const float* __restrict__ X,
                          const float* __restrict__ W1,
                          const float* __restrict__ b1,
                          const float* __restrict__ W2,
                          const float* __restrict__ b2,
                          float* __restrict__ out)
{
    extern __shared__ __align__(1024) unsigned char smraw[];
    const u32 sb = smem_u32(smraw);

    const int ig   = blockIdx.x;            // i-group (0..31)
    const int b    = blockIdx.y;            // batch
    const int tid  = (int)threadIdx.x;
    const int wid  = tid >> 5;
    const int lane = tid & 31;
    const int row0 = wid * 16;              // G1/G2 m-rows
    const int wm   = wid >> 1, wn = wid & 1;
    const int d0   = wn * 32;               // G3 warp tile col origin (j0 = wm*32)

    // ---- one-time staging: W1, W2, biases ----
    {
        const float4* gW1 = (const float4*)W1;   // 1024 each
        const float4* gW2 = (const float4*)W2;
        #pragma unroll
        for (int it = 0; it < 8; ++it) {
            int t = tid + it * 256;              // 0..2047
            int sel = t >> 10;
            int r = t & 1023;
            float4 v = sel ? gW2[r] : gW1[r];
            int d = r >> 4, e0 = (r & 15) * 4;
            sts64(sb + (sel ? OFF_W2 : OFF_W1) + (u32)d * RS64 + (u32)e0 * 2,
                  pack_h16(v.x, v.y), pack_h16(v.z, v.w));
        }
        if (tid < 64)       sts32(sb + OFF_B1 + (u32)tid * 4, __float_as_uint(__ldg(&b1[tid])));
        else if (tid < 128) sts32(sb + OFF_B2 + (u32)(tid - 64) * 4, __float_as_uint(__ldg(&b2[tid - 64])));
    }
    __syncthreads();

    // precomputed addresses
    const u32 aoffX = sb + OFF_X + ((u32)row0 + (u32)(lane & 15)) * RS64 + (u32)(lane >> 4) * 16;
    const u32 boffW = (u32)(lane & 15) * RS64 + (u32)(lane >> 4) * 16;
    const u32 boffH = sb + OFF_H2 + (u32)(lane & 15) * RS64 + (u32)d0 * 2 + (u32)(lane >> 4) * 16;
    // At fragments: jblock = wm*2 + mb; index = ((b*8 + jblock)*8 + ks)*32 + lane
    const uint4* afrag = g_Afrag + (((size_t)b * 8 + (size_t)wm * 2) * 8) * 32 + lane;

    for (int t4 = 0; t4 < I_PER_CTA; ++t4) {
        const size_t tile = (size_t)(b * NN + ig * I_PER_CTA + t4);

        // ---- stage X (fp16) ----
        {
            const float4* gX4 = (const float4*)(X + tile * (NN * DD));  // 2048 float4
            #pragma unroll
            for (int it = 0; it < 8; ++it) {
                int t = tid + it * 256;
                float4 v = gX4[t];
                int k = t >> 4, dq = (t & 15) * 4;
                sts64(sb + OFF_X + (u32)k * RS64 + (u32)dq * 2,
                      pack_h16(v.x, v.y), pack_h16(v.z, v.w));
            }
        }
        __syncthreads();   // bar1: X visible; G3(t-1) h2 readers all past

        // ---- GEMM1: acc1 = X W1  (M=128 N=64 K=64) ----
        float acc1[8][4];
        #pragma unroll
        for (int n = 0; n < 8; ++n)
            #pragma unroll
            for (int q = 0; q < 4; ++q) acc1[n][q] = 0.0f;
        #pragma unroll
        for (int ks = 0; ks < 4; ++ks) {
            u32 fa[4];
            ldsm4(fa, aoffX + (u32)ks * 32);
            const u32 bb = sb + OFF_W1 + (u32)ks * 16 * RS64 + boffW;
            #pragma unroll
            for (int np = 0; np < 4; ++np) {
                u32 fb[4];
                ldsm4t(fb, bb + (u32)np * 32);
                mma_f16(acc1[2 * np],     fa, fb);
                mma_f16(acc1[2 * np + 1], fa, fb + 2);
            }
        }

        // ---- GEMM2: acc2 = relu(acc1 + b1) W2, A-fragments built in registers ----
        float acc2[8][4];
        #pragma unroll
        for (int n = 0; n < 8; ++n)
            #pragma unroll
            for (int q = 0; q < 4; ++q) acc2[n][q] = 0.0f;
        #pragma unroll
        for (int ks = 0; ks < 4; ++ks) {
            float bz0, bz1, bz2, bz3;
            lds64f(bz0, bz1, sb + OFF_B1 + (u32)(16 * ks + 2 * (lane & 3)) * 4);
            lds64f(bz2, bz3, sb + OFF_B1 + (u32)(16 * ks + 8 + 2 * (lane & 3)) * 4);
            u32 fa[4];
            fa[0] = pack_h16(fmaxf(acc1[2 * ks][0] + bz0, 0.f), fmaxf(acc1[2 * ks][1] + bz1, 0.f));
            fa[1] = pack_h16(fmaxf(acc1[2 * ks][2] + bz0, 0.f), fmaxf(acc1[2 * ks][3] + bz1, 0.f));
            fa[2] = pack_h16(fmaxf(acc1[2 * ks + 1][0] + bz2, 0.f), fmaxf(acc1[2 * ks + 1][1] + bz3, 0.f));
            fa[3] = pack_h16(fmaxf(acc1[2 * ks + 1][2] + bz2, 0.f), fmaxf(acc1[2 * ks + 1][3] + bz3, 0.f));
            const u32 bb = sb + OFF_W2 + (u32)ks * 16 * RS64 + boffW;
            #pragma unroll
            for (int np = 0; np < 4; ++np) {
                u32 fb[4];
                ldsm4t(fb, bb + (u32)np * 32);
                mma_f16(acc2[2 * np],     fa, fb);
                mma_f16(acc2[2 * np + 1], fa, fb + 2);
            }
        }

        // ---- h2 = relu(acc2 + b2) -> smem fp16 ----
        {
            const int r  = row0 + (lane >> 2);
            const int cb = 2 * (lane & 3);
            #pragma unroll
            for (int n0 = 0; n0 < 8; ++n0) {
                const int col = n0 * 8 + cb;
                float bz0, bz1;
                lds64f(bz0, bz1, sb + OFF_B2 + (u32)col * 4);
                float v0 = fmaxf(acc2[n0][0] + bz0, 0.f);
                float v1 = fmaxf(acc2[n0][1] + bz1, 0.f);
                float v2 = fmaxf(acc2[n0][2] + bz0, 0.f);
                float v3 = fmaxf(acc2[n0][3] + bz1, 0.f);
                const u32 a0 = sb + OFF_H2 + (u32)r * RS64 + (u32)col * 2;
                sts32(a0,             pack_h16(v0, v1));
                sts32(a0 + 8u * RS64, pack_h16(v2, v3));
            }
        }
        __syncthreads();   // bar2: h2 visible

        // ---- GEMM3: out[j][d] = sum_k At[j][k] h2[k][d]  (warp tile 32x32) ----
        float acc3[8][4];
        #pragma unroll
        for (int n = 0; n < 8; ++n)
            #pragma unroll
            for (int q = 0; q < 4; ++q) acc3[n][q] = 0.0f;
        #pragma unroll
        for (int ks = 0; ks < 8; ++ks) {
            uint4 A0 = __ldg(&afrag[(size_t)ks * 32]);          // jblock = wm*2
            uint4 A1 = __ldg(&afrag[(size_t)(8 + ks) * 32]);    // jblock = wm*2 + 1
            u32 fa0[4] = {A0.x, A0.y, A0.z, A0.w};
            u32 fa1[4] = {A1.x, A1.y, A1.z, A1.w};
            u32 fb0[4], fb1[4];
            const u32 bb = boffH + (u32)ks * 16 * RS64;
            ldsm4t(fb0, bb);
            ldsm4t(fb1, bb + 32);
            mma_f16(acc3[0], fa0, fb0); mma_f16(acc3[1], fa0, fb0 + 2);
            mma_f16(acc3[2], fa0, fb1); mma_f16(acc3[3], fa0, fb1 + 2);
            mma_f16(acc3[4], fa1, fb0); mma_f16(acc3[5], fa1, fb0 + 2);
            mma_f16(acc3[6], fa1, fb1); mma_f16(acc3[7], fa1, fb1 + 2);
        }

        // ---- store to global ----
        {
            float* gO = out + tile * (NN * DD);
            const int gr = lane >> 2, cb = 2 * (lane & 3);
            #pragma unroll
            for (int mb = 0; mb < 2; ++mb) {
                const int j = wm * 32 + 16 * mb + gr;
                #pragma unroll
                for (int nb = 0; nb < 4; ++nb) {
                    const float* a = acc3[mb * 4 + nb];
                    const int col = d0 + 8 * nb + cb;
                    *(float2*)(gO + (size_t)j * DD + col)       = make_float2(a[0], a[1]);
                    *(float2*)(gO + (size_t)(j + 8) * DD + col) = make_float2(a[2], a[3]);
                }
            }
        }
        // next iteration's X staging is safe: everyone passed bar2 (G1/G2 done),
        // and G3 reads only g_Afrag (global) + h2.
    }
}

extern "C" void kernel_launch(void* const* d_in, const int* in_sizes, int n_in,
                              void* d_out, int out_size)
{
    const float *X = nullptr, *A = nullptr, *W1 = nullptr, *b1 = nullptr,
                *W2 = nullptr, *b2 = nullptr;
    for (int idx = 0; idx < n_in; ++idx) {
        const float* p = (const float*)d_in[idx];
        int s = in_sizes[idx];
        if      (s == NB * NN * NN * DD) X = p;
        else if (s == NB * NN * NN)      A = p;
        else if (s == DD * DD)           { if (!W1) W1 = p; else W2 = p; }
        else if (s == DD)                { if (!b1) b1 = p; else b2 = p; }
    }

    prep_Afrag<<<256, 256>>>(A);   // 65536 threads

    cudaFuncSetAttribute(crosssubg_mma_kernel,
                         cudaFuncAttributeMaxDynamicSharedMemorySize, SMEM_BYTES);
    dim3 grid(NN / I_PER_CTA, NB);   // (32, 32)
    crosssubg_mma_kernel<<<grid, 256, SMEM_BYTES>>>(X, W1, b1, W2, b2, (float*)d_out);
}

// round 8
// speedup vs baseline: 1.3290x; 1.3290x over previous
#include <cuda_runtime.h>
#include <cuda_fp16.h>
#include <cstdint>

typedef uint32_t u32;

static constexpr int NB = 32, NN = 128, DD = 64;

// Precomputed A-transpose fp16 image: At[j][k] = A[b][k][j],
// 128 rows, row stride 136 fp16 (272B), 128 valid k + pad.
__device__ __align__(16) unsigned char g_Ah[32][34816];

// ---------------- helpers ----------------
__device__ __forceinline__ u32 smem_u32(const void* p) {
    u32 a;
    asm("{ .reg .u64 t; cvta.to.shared.u64 t, %1; cvt.u32.u64 %0, t; }" : "=r"(a) : "l"(p));
    return a;
}
__device__ __forceinline__ u32 pack_h16(float lo, float hi) {
    u32 r;
    asm("cvt.rn.f16x2.f32 %0, %1, %2;" : "=r"(r) : "f"(hi), "f"(lo));
    return r;
}
__device__ __forceinline__ void sts32(u32 a, u32 v) {
    asm volatile("st.shared.b32 [%0], %1;" :: "r"(a), "r"(v) : "memory");
}
__device__ __forceinline__ void sts64(u32 a, u32 x, u32 y) {
    asm volatile("st.shared.v2.b32 [%0], {%1,%2};" :: "r"(a), "r"(x), "r"(y) : "memory");
}
__device__ __forceinline__ void sts128(u32 a, u32 x, u32 y, u32 z, u32 w) {
    asm volatile("st.shared.v4.b32 [%0], {%1,%2,%3,%4};" :: "r"(a), "r"(x), "r"(y), "r"(z), "r"(w) : "memory");
}
__device__ __forceinline__ void lds64f(float& x, float& y, u32 a) {
    asm volatile("ld.shared.v2.f32 {%0,%1}, [%2];" : "=f"(x), "=f"(y) : "r"(a));
}
__device__ __forceinline__ void ldsm4(u32* f, u32 a) {
    asm volatile("ldmatrix.sync.aligned.m8n8.x4.shared.b16 {%0,%1,%2,%3}, [%4];"
                 : "=r"(f[0]), "=r"(f[1]), "=r"(f[2]), "=r"(f[3]) : "r"(a));
}
__device__ __forceinline__ void ldsm4t(u32* f, u32 a) {
    asm volatile("ldmatrix.sync.aligned.m8n8.x4.trans.shared.b16 {%0,%1,%2,%3}, [%4];"
                 : "=r"(f[0]), "=r"(f[1]), "=r"(f[2]), "=r"(f[3]) : "r"(a));
}
__device__ __forceinline__ void mma_f16(float* c, const u32* a, const u32* b) {
    asm volatile(
        "mma.sync.aligned.m16n8k16.row.col.f32.f16.f16.f32 "
        "{%0,%1,%2,%3}, {%4,%5,%6,%7}, {%8,%9}, {%0,%1,%2,%3};"
        : "+f"(c[0]), "+f"(c[1]), "+f"(c[2]), "+f"(c[3])
        : "r"(a[0]), "r"(a[1]), "r"(a[2]), "r"(a[3]), "r"(b[0]), "r"(b[1]));
}

// ---------------- smem layout ----------------
static constexpr u32 RS64  = 144;   // 64-wide fp16 tile row stride (bytes)
static constexpr u32 RS128 = 272;   // 128-wide tile row stride

static constexpr u32 OFF_W1 = 0;        // 9216
static constexpr u32 OFF_W2 = 9216;     // 9216
static constexpr u32 OFF_AT = 18432;    // 34816
static constexpr u32 OFF_H2 = 53248;    // 18432
static constexpr u32 OFF_B1 = 71680;    // 256
static constexpr u32 OFF_B2 = 71936;    // 256
static constexpr u32 SMEM_BYTES = 72192;

static constexpr int I_PER_CTA = 4;

// =============== prep: A[b][k][j] -> At fp16 image ===============
__global__ void prep_At(const float* __restrict__ A)
{
    __shared__ float tile[32][33];
    const int b = blockIdx.z, k0 = blockIdx.x * 32, j0 = blockIdx.y * 32;
    const int tx = threadIdx.x & 31, ty = threadIdx.x >> 5;   // ty: 0..7

    const float* Ab = A + ((size_t)b * NN + k0) * NN + j0;
    #pragma unroll
    for (int s = 0; s < 4; ++s)
        tile[ty + 8 * s][tx] = Ab[(ty + 8 * s) * NN + tx];
    __syncthreads();

    const int j  = threadIdx.x >> 3;   // 0..31
    const int kq = threadIdx.x & 7;    // 4 k values each
    float v[4];
    #pragma unroll
    for (int s = 0; s < 4; ++s) v[s] = tile[kq * 4 + s][j];

    uint2 h = make_uint2(pack_h16(v[0], v[1]), pack_h16(v[2], v[3]));
    size_t off = (size_t)(j0 + j) * RS128 + (size_t)(k0 + kq * 4) * 2;
    *reinterpret_cast<uint2*>(&g_Ah[b][off]) = h;
}

// =============== main fused kernel ===============
__global__ __launch_bounds__(256, 3)
void crosssubg_mma_kernel(const float* __restrict__ X,
                          const float* __restrict__ W1,
                          const float* __restrict__ b1,
                          const float* __restrict__ W2,
                          const float* __restrict__ b2,
                          float* __restrict__ out)
{
    extern __shared__ __align__(256) unsigned char smraw[];
    const u32 sb = smem_u32(smraw);

    const int ig   = blockIdx.x;            // i-group (0..31)
    const int b    = blockIdx.y;            // batch
    const int tid  = (int)threadIdx.x;
    const int wid  = tid >> 5;
    const int lane = tid & 31;
    const int row0 = wid * 16;              // G1/G2 m-rows
    const int wm   = wid >> 1, wn = wid & 1;
    const int j0   = wm * 32, d0 = wn * 32; // G3 warp tile origin

    // ---- one-time staging: W1, W2, At, biases ----
    {
        const float4* gW1 = (const float4*)W1;   // 1024 each
        const float4* gW2 = (const float4*)W2;
        #pragma unroll
        for (int it = 0; it < 8; ++it) {
            int t = tid + it * 256;              // 0..2047
            int sel = t >> 10;
            int r = t & 1023;
            float4 v = sel ? gW2[r] : gW1[r];
            int d = r >> 4, e0 = (r & 15) * 4;
            sts64(sb + (sel ? OFF_W2 : OFF_W1) + (u32)d * RS64 + (u32)e0 * 2,
                  pack_h16(v.x, v.y), pack_h16(v.z, v.w));
        }
        const uint4* gA = (const uint4*)&g_Ah[b][0];   // 2176 uint4
        #pragma unroll
        for (int it = 0; it < 9; ++it) {
            int t = tid + it * 256;
            if (t < 2176) {
                uint4 v = gA[t];
                sts128(sb + OFF_AT + (u32)t * 16, v.x, v.y, v.z, v.w);
            }
        }
        if (tid < 64)       sts32(sb + OFF_B1 + (u32)tid * 4, __float_as_uint(__ldg(&b1[tid])));
        else if (tid < 128) sts32(sb + OFF_B2 + (u32)(tid - 64) * 4, __float_as_uint(__ldg(&b2[tid - 64])));
    }
    __syncthreads();

    // precomputed addresses
    const int fr = lane >> 2, fc = lane & 3;      // fragment row/col-pair within 16x16
    const u32 boffW = (u32)(lane & 15) * RS64 + (u32)(lane >> 4) * 16;
    const u32 aoffA = sb + OFF_AT + ((u32)j0 + (u32)(lane & 15)) * RS128 + (u32)(lane >> 4) * 16;
    const u32 boffH = sb + OFF_H2 + (u32)(lane & 15) * RS64 + (u32)d0 * 2 + (u32)(lane >> 4) * 16;

    for (int t4 = 0; t4 < I_PER_CTA; ++t4) {
        const size_t tile = (size_t)(b * NN + ig * I_PER_CTA + t4);
        const float2* gX2 = (const float2*)(X + tile * (NN * DD));   // [128][32] float2

        // ---- G1 X A-fragments: bulk global loads (16 independent LDG.64) ----
        float2 xv[4][4];
        {
            const int ra = (row0 + fr) * 32 + fc;       // row r,   float2 index base
            const int rb = (row0 + fr + 8) * 32 + fc;   // row r+8
            #pragma unroll
            for (int ks = 0; ks < 4; ++ks) {
                xv[ks][0] = __ldg(&gX2[ra + 8 * ks]);
                xv[ks][1] = __ldg(&gX2[rb + 8 * ks]);
                xv[ks][2] = __ldg(&gX2[ra + 8 * ks + 4]);
                xv[ks][3] = __ldg(&gX2[rb + 8 * ks + 4]);
            }
        }

        // ---- GEMM1: acc1 = X W1  (M=128 N=64 K=64) ----
        float acc1[8][4];
        #pragma unroll
        for (int n = 0; n < 8; ++n)
            #pragma unroll
            for (int q = 0; q < 4; ++q) acc1[n][q] = 0.0f;
        #pragma unroll
        for (int ks = 0; ks < 4; ++ks) {
            u32 fa[4];
            fa[0] = pack_h16(xv[ks][0].x, xv[ks][0].y);
            fa[1] = pack_h16(xv[ks][1].x, xv[ks][1].y);
            fa[2] = pack_h16(xv[ks][2].x, xv[ks][2].y);
            fa[3] = pack_h16(xv[ks][3].x, xv[ks][3].y);
            const u32 bb = sb + OFF_W1 + (u32)ks * 16 * RS64 + boffW;
            #pragma unroll
            for (int np = 0; np < 4; ++np) {
                u32 fb[4];
                ldsm4t(fb, bb + (u32)np * 32);
                mma_f16(acc1[2 * np],     fa, fb);
                mma_f16(acc1[2 * np + 1], fa, fb + 2);
            }
        }

        // ---- GEMM2: acc2 = relu(acc1 + b1) W2, A-fragments built in registers ----
        float acc2[8][4];
        #pragma unroll
        for (int n = 0; n < 8; ++n)
            #pragma unroll
            for (int q = 0; q < 4; ++q) acc2[n][q] = 0.0f;
        #pragma unroll
        for (int ks = 0; ks < 4; ++ks) {
            float bz0, bz1, bz2, bz3;
            lds64f(bz0, bz1, sb + OFF_B1 + (u32)(16 * ks + 2 * fc) * 4);
            lds64f(bz2, bz3, sb + OFF_B1 + (u32)(16 * ks + 8 + 2 * fc) * 4);
            u32 fa[4];
            fa[0] = pack_h16(fmaxf(acc1[2 * ks][0] + bz0, 0.f), fmaxf(acc1[2 * ks][1] + bz1, 0.f));
            fa[1] = pack_h16(fmaxf(acc1[2 * ks][2] + bz0, 0.f), fmaxf(acc1[2 * ks][3] + bz1, 0.f));
            fa[2] = pack_h16(fmaxf(acc1[2 * ks + 1][0] + bz2, 0.f), fmaxf(acc1[2 * ks + 1][1] + bz3, 0.f));
            fa[3] = pack_h16(fmaxf(acc1[2 * ks + 1][2] + bz2, 0.f), fmaxf(acc1[2 * ks + 1][3] + bz3, 0.f));
            const u32 bb = sb + OFF_W2 + (u32)ks * 16 * RS64 + boffW;
            #pragma unroll
            for (int np = 0; np < 4; ++np) {
                u32 fb[4];
                ldsm4t(fb, bb + (u32)np * 32);
                mma_f16(acc2[2 * np],     fa, fb);
                mma_f16(acc2[2 * np + 1], fa, fb + 2);
            }
        }

        __syncthreads();   // bar-A: all warps done reading h2(t-1) in G3

        // ---- h2 = relu(acc2 + b2) -> smem fp16 ----
        {
            const int r  = row0 + fr;
            const int cb = 2 * fc;
            #pragma unroll
            for (int n0 = 0; n0 < 8; ++n0) {
                const int col = n0 * 8 + cb;
                float bz0, bz1;
                lds64f(bz0, bz1, sb + OFF_B2 + (u32)col * 4);
                float v0 = fmaxf(acc2[n0][0] + bz0, 0.f);
                float v1 = fmaxf(acc2[n0][1] + bz1, 0.f);
                float v2 = fmaxf(acc2[n0][2] + bz0, 0.f);
                float v3 = fmaxf(acc2[n0][3] + bz1, 0.f);
                const u32 a0 = sb + OFF_H2 + (u32)r * RS64 + (u32)col * 2;
                sts32(a0,             pack_h16(v0, v1));
                sts32(a0 + 8u * RS64, pack_h16(v2, v3));
            }
        }
        __syncthreads();   // bar-B: h2 visible

        // ---- GEMM3: out[j][d] = sum_k At[j][k] h2[k][d]  (warp tile 32x32) ----
        float acc3[8][4];
        #pragma unroll
        for (int n = 0; n < 8; ++n)
            #pragma unroll
            for (int q = 0; q < 4; ++q) acc3[n][q] = 0.0f;
        #pragma unroll
        for (int ks = 0; ks < 8; ++ks) {
            u32 fa0[4], fa1[4], fb0[4], fb1[4];
            ldsm4(fa0, aoffA + (u32)ks * 32);
            ldsm4(fa1, aoffA + 16u * RS128 + (u32)ks * 32);
            const u32 bb = boffH + (u32)ks * 16 * RS64;
            ldsm4t(fb0, bb);
            ldsm4t(fb1, bb + 32);
            mma_f16(acc3[0], fa0, fb0); mma_f16(acc3[1], fa0, fb0 + 2);
            mma_f16(acc3[2], fa0, fb1); mma_f16(acc3[3], fa0, fb1 + 2);
            mma_f16(acc3[4], fa1, fb0); mma_f16(acc3[5], fa1, fb0 + 2);
            mma_f16(acc3[6], fa1, fb1); mma_f16(acc3[7], fa1, fb1 + 2);
        }

        // ---- store to global ----
        {
            float* gO = out + tile * (NN * DD);
            const int cb = 2 * fc;
            #pragma unroll
            for (int mb = 0; mb < 2; ++mb) {
                const int j = j0 + 16 * mb + fr;
                #pragma unroll
                for (int nb = 0; nb < 4; ++nb) {
                    const float* a = acc3[mb * 4 + nb];
                    const int col = d0 + 8 * nb + cb;
                    *(float2*)(gO + (size_t)j * DD + col)       = make_float2(a[0], a[1]);
                    *(float2*)(gO + (size_t)(j + 8) * DD + col) = make_float2(a[2], a[3]);
                }
            }
        }
    }
}

extern "C" void kernel_launch(void* const* d_in, const int* in_sizes, int n_in,
                              void* d_out, int out_size)
{
    const float *X = nullptr, *A = nullptr, *W1 = nullptr, *b1 = nullptr,
                *W2 = nullptr, *b2 = nullptr;
    for (int idx = 0; idx < n_in; ++idx) {
        const float* p = (const float*)d_in[idx];
        int s = in_sizes[idx];
        if      (s == NB * NN * NN * DD) X = p;
        else if (s == NB * NN * NN)      A = p;
        else if (s == DD * DD)           { if (!W1) W1 = p; else W2 = p; }
        else if (s == DD)                { if (!b1) b1 = p; else b2 = p; }
    }

    prep_At<<<dim3(4, 4, 32), 256>>>(A);

    cudaFuncSetAttribute(crosssubg_mma_kernel,
                         cudaFuncAttributeMaxDynamicSharedMemorySize, SMEM_BYTES);
    dim3 grid(NN / I_PER_CTA, NB);   // (32, 32)
    crosssubg_mma_kernel<<<grid, 256, SMEM_BYTES>>>(X, W1, b1, W2, b2, (float*)d_out);
}